// round 2
// baseline (speedup 1.0000x reference)
#include <cuda_runtime.h>

// MultiStageFIRFilter: y = x + sum_{a=1..20} xa_a,
//   xa_a[b,t] = (1/a) * sum_{k=0..24} mc[b,t,k] * xa_{a-1}[b,t-k]  (xa_0 = x, causal)
//
// Fused halo-recompute kernel with stage-dependent compute trimming:
// at stage a, only local positions >= 24*a are needed by any later consumer,
// so threads with tid < 12*a skip the stage entirely.

#define NB      4
#define NT      16384
#define M       25
#define STAGES  20
#define HALO    480       // STAGES * (M-1)
#define THREADS 512
#define EXT     1024      // positions per block (2 per thread)
#define TILE    544       // EXT - HALO
#define PAD     24
#define NTILES  31        // ceil(16384 / 544)

__global__ __launch_bounds__(THREADS, 1)
void fir_kernel(const float* __restrict__ x, const float* __restrict__ mc,
                float* __restrict__ out)
{
    __shared__ __align__(16) float s0[PAD + EXT];
    __shared__ __align__(16) float s1[PAD + EXT];

    const int tile = blockIdx.x % NTILES;
    const int b    = blockIdx.x / NTILES;
    const int t0   = tile * TILE;
    const int tid  = threadIdx.x;
    const int i0   = 2 * tid;              // local position (even)
    const int p0   = t0 - HALO + i0;       // global time of first owned position
    const size_t rowbase = (size_t)b * NT;

    if (tid < PAD) { s0[tid] = 0.0f; s1[tid] = 0.0f; }

    // ---- per-position coefficients in registers (2 rows x 25) ----
    float c0[25], c1[25];
    if (p0 >= 0 && p0 + 1 < NT) {
        const float2* g = (const float2*)(mc + (rowbase + (size_t)p0) * M);
        float t[50];
        #pragma unroll
        for (int k = 0; k < 25; k++) { float2 v = g[k]; t[2*k] = v.x; t[2*k+1] = v.y; }
        #pragma unroll
        for (int k = 0; k < 25; k++) { c0[k] = t[k]; c1[k] = t[25 + k]; }
    } else {
        #pragma unroll
        for (int k = 0; k < 25; k++) { c0[k] = 0.0f; c1[k] = 0.0f; }
        if (p0 >= 0 && p0 < NT) {
            const float* g = mc + (rowbase + (size_t)p0) * M;
            #pragma unroll
            for (int k = 0; k < 25; k++) c0[k] = g[k];
        }
        if (p0 + 1 >= 0 && p0 + 1 < NT) {
            const float* g = mc + (rowbase + (size_t)(p0 + 1)) * M;
            #pragma unroll
            for (int k = 0; k < 25; k++) c1[k] = g[k];
        }
    }

    // ---- stage 0 ----
    float v0 = (p0     >= 0 && p0     < NT) ? x[rowbase + p0]     : 0.0f;
    float v1 = (p0 + 1 >= 0 && p0 + 1 < NT) ? x[rowbase + p0 + 1] : 0.0f;
    float y0 = v0, y1 = v1;

    ((float2*)(s0 + PAD))[tid] = make_float2(v0, v1);
    __syncthreads();

    float* cur = s0;
    float* nxt = s1;
    const bool ghost = (p0 < 0);   // t<0 positions: xa stays exactly 0

    #pragma unroll
    for (int a = 1; a <= STAGES; a++) {
        const float inv = 1.0f / (float)a;      // compile-time constant (unrolled)
        if (tid >= 12 * a) {                    // stage-dependent trim
            // window w[j] = xa_{a-1}[local i0-24+j], j=0..23 (own 2 values stay in regs)
            float w[24];
            const float2* wp = (const float2*)(cur + i0);
            #pragma unroll
            for (int j = 0; j < 12; j++) { float2 v = wp[j]; w[2*j] = v.x; w[2*j+1] = v.y; }

            // out p0:   sum_k c0[k] * val(p0-k);  val(p0)=v0, val(p0-k)=w[24-k]
            float pA = c0[0] * v0, pB = 0.0f;
            #pragma unroll
            for (int k = 1; k <= 12; k++)  pA = fmaf(c0[k], w[24 - k], pA);
            #pragma unroll
            for (int k = 13; k <= 24; k++) pB = fmaf(c0[k], w[24 - k], pB);

            // out p0+1: val(p0+1)=v1, val(p0)=v0, val(p0+1-k)=w[25-k] for k>=2
            float qA = fmaf(c1[1], v0, c1[0] * v1), qB = 0.0f;
            #pragma unroll
            for (int k = 2; k <= 13; k++)  qA = fmaf(c1[k], w[25 - k], qA);
            #pragma unroll
            for (int k = 14; k <= 24; k++) qB = fmaf(c1[k], w[25 - k], qB);

            float acc0 = (pA + pB) * inv;
            float acc1 = (qA + qB) * inv;
            if (ghost) { acc0 = 0.0f; acc1 = 0.0f; }
            y0 += acc0; y1 += acc1;
            v0 = acc0;  v1 = acc1;
            ((float2*)(nxt + PAD))[tid] = make_float2(v0, v1);
        }
        __syncthreads();
        float* tmp = cur; cur = nxt; nxt = tmp;
    }

    // ---- write owned (non-halo) outputs ----
    if (i0 >= HALO && p0 < NT) {
        out[rowbase + p0] = y0;
        if (p0 + 1 < NT) out[rowbase + p0 + 1] = y1;
    }
}

extern "C" void kernel_launch(void* const* d_in, const int* in_sizes, int n_in,
                              void* d_out, int out_size)
{
    const float* x  = (const float*)d_in[0];   // (4, 16384) float32
    const float* mc = (const float*)d_in[1];   // (4, 16384, 25) float32
    float* out = (float*)d_out;                // (4, 16384) float32
    fir_kernel<<<NB * NTILES, THREADS>>>(x, mc, out);
}